// round 14
// baseline (speedup 1.0000x reference)
#include <cuda_runtime.h>
#include <cuda_bf16.h>
#include <stdint.h>
#include <math.h>

#define BB 8
#define TT 1024
#define DD 512
#define HH 8
#define DH 64
#define MM 1024
#define BT (BB*TT)

// ---------------- scratch (device globals; allocation-free) ----------------
__device__ __align__(16) __nv_bfloat16 g_xb[BT*DD];          // LN output bf16 [bt][d]
__device__ __align__(16) __nv_bfloat16 g_pb[BT*DD];          // pos bf16 [bt][d]
__device__ __align__(16) __nv_bfloat16 g_wt[4*HH*DH*DD];     // weights [m][h][n][k] bf16
__device__ __align__(16) __nv_bfloat16 g_wo[DD*DD];          // out-proj [d][k] bf16
__device__ __align__(16) __nv_bfloat16 g_qu[BB*HH*TT*DH];    // q + pbu  [bh][t][dh]
__device__ __align__(16) __nv_bfloat16 g_qv[BB*HH*TT*DH];    // q + pbv
__device__ __align__(16) __nv_bfloat16 g_kb[BB*HH*TT*DH];    // k
__device__ __align__(16) __nv_bfloat16 g_vb[BB*HH*TT*DH];    // v
__device__ __align__(16) __nv_bfloat16 g_ph[BB*HH*TT*DH];    // projected pos
__device__ __align__(16) __nv_bfloat16 g_ob[BT*DD];          // attn out [b][t][h][dh]
__device__ __align__(16) __nv_bfloat16 g_sv[(size_t)BB*HH*TT*MM];  // SHIFTED pos logits bf16

// ---------------- helpers ----------------
__device__ __forceinline__ uint32_t pbf(float lo, float hi) {
    uint32_t r;
    asm volatile("cvt.rn.bf16x2.f32 %0, %1, %2;" : "=r"(r) : "f"(hi), "f"(lo));
    return r;
}

__device__ __forceinline__ void mma16(float* d, const uint32_t* a, const uint32_t* b) {
    asm volatile(
        "mma.sync.aligned.m16n8k16.row.col.f32.bf16.bf16.f32 "
        "{%0,%1,%2,%3}, {%4,%5,%6,%7}, {%8,%9}, {%0,%1,%2,%3};\n"
        : "+f"(d[0]), "+f"(d[1]), "+f"(d[2]), "+f"(d[3])
        : "r"(a[0]), "r"(a[1]), "r"(a[2]), "r"(a[3]), "r"(b[0]), "r"(b[1]));
}

__device__ __forceinline__ void ldsm4(uint32_t* r, uint32_t addr) {
    asm volatile("ldmatrix.sync.aligned.m8n8.x4.shared.b16 {%0,%1,%2,%3}, [%4];"
                 : "=r"(r[0]), "=r"(r[1]), "=r"(r[2]), "=r"(r[3]) : "r"(addr));
}
__device__ __forceinline__ void ldsm4t(uint32_t* r, uint32_t addr) {
    asm volatile("ldmatrix.sync.aligned.m8n8.x4.trans.shared.b16 {%0,%1,%2,%3}, [%4];"
                 : "=r"(r[0]), "=r"(r[1]), "=r"(r[2]), "=r"(r[3]) : "r"(addr));
}

// A-fragment 16x16 bf16 from [row][k-pair] layout
__device__ __forceinline__ void ldsmA(uint32_t* a, const uint32_t* S, int rowbase,
                                      int kw, int ldw, int lane) {
    const int t = lane >> 3, rr = lane & 7;
    const uint32_t* p = S + (size_t)(rowbase + ((t & 1) << 3) + rr) * ldw + kw + ((t >> 1) << 2);
    ldsm4(a, (uint32_t)__cvta_generic_to_shared(p));
}
// B-fragments for two n-blocks from [n][k-pair] layout
__device__ __forceinline__ void ldsmB(uint32_t* b, const uint32_t* S, int nbase,
                                      int kw, int ldw, int lane) {
    const int t = lane >> 3, rr = lane & 7;
    const uint32_t* p = S + (size_t)(nbase + ((t >> 1) << 3) + rr) * ldw + kw + ((t & 1) << 2);
    ldsm4(b, (uint32_t)__cvta_generic_to_shared(p));
}
// B-fragments for two n-blocks from [k][n-pair] layout via ldmatrix.trans
__device__ __forceinline__ void ldsmBT(uint32_t* b, const uint32_t* S, int nbase,
                                       int kw, int ldw, int lane) {
    const int t = lane >> 3, rr = lane & 7;
    const uint32_t* p = S + (size_t)(kw*2 + ((t & 1) << 3) + rr) * ldw + (nbase >> 1) + ((t >> 1) << 2);
    ldsm4t(b, (uint32_t)__cvta_generic_to_shared(p));
}

__device__ __forceinline__ void cp16(uint32_t saddr, const void* gptr) {
    asm volatile("cp.async.cg.shared.global [%0], [%1], 16;" :: "r"(saddr), "l"(gptr));
}
__device__ __forceinline__ void cp_commit() { asm volatile("cp.async.commit_group;"); }
template<int N> __device__ __forceinline__ void cp_wait() {
    asm volatile("cp.async.wait_group %0;" :: "n"(N));
}

// ---------------- kernel 1: LayerNorm -> bf16 ----------------
__global__ void ln_kernel(const float* __restrict__ in,
                          const float* __restrict__ gamma,
                          const float* __restrict__ beta) {
    const int row = blockIdx.x;
    const int tid = threadIdx.x;
    const float2 v = ((const float2*)(in + (size_t)row * DD))[tid];
    __shared__ float red[8];

    float s = v.x + v.y;
    #pragma unroll
    for (int o = 16; o; o >>= 1) s += __shfl_xor_sync(0xffffffffu, s, o);
    if ((tid & 31) == 0) red[tid >> 5] = s;
    __syncthreads();
    float mean = 0.f;
    #pragma unroll
    for (int i = 0; i < 8; i++) mean += red[i];
    mean *= (1.0f / DD);
    __syncthreads();

    const float dx = v.x - mean, dy = v.y - mean;
    float sq = dx*dx + dy*dy;
    #pragma unroll
    for (int o = 16; o; o >>= 1) sq += __shfl_xor_sync(0xffffffffu, sq, o);
    if ((tid & 31) == 0) red[tid >> 5] = sq;
    __syncthreads();
    float var = 0.f;
    #pragma unroll
    for (int i = 0; i < 8; i++) var += red[i];
    var *= (1.0f / DD);

    const float inv = rsqrtf(var + 1e-3f);
    const int c0 = tid * 2;
    const float y0 = dx * inv * gamma[c0]   + beta[c0];
    const float y1 = dy * inv * gamma[c0+1] + beta[c0+1];
    ((uint32_t*)g_xb)[row * (DD/2) + tid] = pbf(y0, y1);
}

// ---------------- converters ----------------
__global__ void cvt_pos(const float* __restrict__ pos) {
    const int w = blockIdx.x * 256 + threadIdx.x;
    const float2 v = ((const float2*)pos)[w];
    ((uint32_t*)g_pb)[w] = pbf(v.x, v.y);
}

// weights [H][D][DH] -> g_wt [m][h][n][k]; 32x32 smem-tile transpose
__global__ void cvt_wt(const float* __restrict__ wq, const float* __restrict__ wk,
                       const float* __restrict__ wv, const float* __restrict__ wp) {
    __shared__ float tile[32][33];
    const int mh = blockIdx.z, m = mh >> 3, h = mh & 7;
    const int k0 = blockIdx.x * 32, n0 = blockIdx.y * 32;
    const float* W = (m == 0) ? wq : (m == 1) ? wk : (m == 2) ? wv : wp;
    const int tx = threadIdx.x, ty = threadIdx.y;   // 32 x 8
    #pragma unroll
    for (int i = 0; i < 4; i++) {
        const int k = k0 + ty + i*8;
        tile[ty + i*8][tx] = W[((size_t)h*DD + k)*DH + n0 + tx];  // coalesced over n
    }
    __syncthreads();
    #pragma unroll
    for (int i = 0; i < 4; i++) {
        const int n = n0 + ty + i*8;
        g_wt[((size_t)(mh*DH + n))*DD + k0 + tx] = __float2bfloat16(tile[tx][ty + i*8]);
    }
}

// proj_k [D][D] (k-major rows) -> g_wo [d][k]; 32x32 smem-tile transpose
__global__ void cvt_wo(const float* __restrict__ projk) {
    __shared__ float tile[32][33];
    const int k0 = blockIdx.x * 32, d0 = blockIdx.y * 32;
    const int tx = threadIdx.x, ty = threadIdx.y;   // 32 x 8
    #pragma unroll
    for (int i = 0; i < 4; i++) {
        const int k = k0 + ty + i*8;
        tile[ty + i*8][tx] = projk[(size_t)k*DD + d0 + tx];       // coalesced over d
    }
    __syncthreads();
    #pragma unroll
    for (int i = 0; i < 4; i++) {
        const int d = d0 + ty + i*8;
        g_wo[(size_t)d*DD + k0 + tx] = __float2bfloat16(tile[tx][ty + i*8]);
    }
}

// ---------------- kernel 2: merged projections (q,k,v,p) ----------------
__global__ __launch_bounds__(256) void proj_all(const float* __restrict__ b_q,
                                                const float* __restrict__ b_k,
                                                const float* __restrict__ b_v,
                                                const float* __restrict__ pbu,
                                                const float* __restrict__ pbv) {
    __shared__ uint32_t As[2][128][20];
    __shared__ uint32_t Bs[2][128][20];

    const int bt0 = blockIdx.x * 128;
    const int y = blockIdx.y, m = y >> 2, h0 = (y & 3) * 2;
    const __nv_bfloat16* Asrc = (m == 3) ? g_pb : g_xb;
    const int tid = threadIdx.x, lane = tid & 31, warp = tid >> 5;
    const int g = lane >> 2, tg = lane & 3;
    const int wr = (warp >> 1) * 32, wc = (warp & 1) * 64;

    const uint32_t sA = (uint32_t)__cvta_generic_to_shared(&As[0][0][0]);
    const uint32_t sB = (uint32_t)__cvta_generic_to_shared(&Bs[0][0][0]);

    auto fill = [&](int st, int k0) {
        #pragma unroll
        for (int i = 0; i < 2; i++) {
            const int c = tid + i*256;
            const int row = c >> 2, cw = (c & 3) * 4;
            cp16(sA + ((st*128 + row)*20 + cw)*4,
                 Asrc + (size_t)(bt0 + row)*DD + k0 + cw*2);
            const int h = h0 + (row >> 6), n = row & 63;
            cp16(sB + ((st*128 + row)*20 + cw)*4,
                 g_wt + ((size_t)((m*HH + h)*DH + n))*DD + k0 + cw*2);
        }
    };

    float C[2][8][4] = {};
    fill(0, 0); cp_commit();
    for (int kt = 0; kt < 16; kt++) {
        if (kt < 15) { fill((kt+1)&1, (kt+1)*32); cp_commit(); cp_wait<1>(); }
        else cp_wait<0>();
        __syncthreads();
        const uint32_t* pa = &As[kt&1][0][0];
        const uint32_t* pb = &Bs[kt&1][0][0];
        #pragma unroll
        for (int ks = 0; ks < 2; ks++) {
            const int kw = ks * 8;
            uint32_t a0[4], a1[4];
            ldsmA(a0, pa, wr,      kw, 20, lane);
            ldsmA(a1, pa, wr + 16, kw, 20, lane);
            #pragma unroll
            for (int nb = 0; nb < 4; nb++) {
                uint32_t bb[4];
                ldsmB(bb, pb, wc + nb*16, kw, 20, lane);
                mma16(C[0][nb*2],   a0, bb);
                mma16(C[0][nb*2+1], a0, bb+2);
                mma16(C[1][nb*2],   a1, bb);
                mma16(C[1][nb*2+1], a1, bb+2);
            }
        }
        __syncthreads();
    }

    const int b = bt0 >> 10, t0l = bt0 & (TT-1);
    #pragma unroll
    for (int rs = 0; rs < 2; rs++)
        #pragma unroll
        for (int ns = 0; ns < 8; ns++) {
            const int r = wr + rs*16 + g;
            const int col = wc + ns*8 + tg*2;
            const int h = h0 + (col >> 6), dh = col & 63;
            const int t1 = t0l + r, t2 = t1 + 8;
            const size_t e1 = (((size_t)b*HH + h)*TT + t1)*DH + dh;
            const size_t e2 = (((size_t)b*HH + h)*TT + t2)*DH + dh;
            const float c0 = C[rs][ns][0], c1 = C[rs][ns][1];
            const float c2 = C[rs][ns][2], c3 = C[rs][ns][3];
            if (m == 0) {
                const float bq0 = b_q[h*DH+dh], bq1 = b_q[h*DH+dh+1];
                const float u0 = pbu[h*DH+dh], u1 = pbu[h*DH+dh+1];
                const float v0 = pbv[h*DH+dh], v1 = pbv[h*DH+dh+1];
                ((uint32_t*)g_qu)[e1>>1] = pbf(c0+bq0+u0, c1+bq1+u1);
                ((uint32_t*)g_qu)[e2>>1] = pbf(c2+bq0+u0, c3+bq1+u1);
                ((uint32_t*)g_qv)[e1>>1] = pbf(c0+bq0+v0, c1+bq1+v1);
                ((uint32_t*)g_qv)[e2>>1] = pbf(c2+bq0+v0, c3+bq1+v1);
            } else if (m == 1) {
                const float bk0 = b_k[h*DH+dh], bk1 = b_k[h*DH+dh+1];
                ((uint32_t*)g_kb)[e1>>1] = pbf(c0+bk0, c1+bk1);
                ((uint32_t*)g_kb)[e2>>1] = pbf(c2+bk0, c3+bk1);
            } else if (m == 2) {
                const float bv0 = b_v[h*DH+dh], bv1 = b_v[h*DH+dh+1];
                ((uint32_t*)g_vb)[e1>>1] = pbf(c0+bv0, c1+bv1);
                ((uint32_t*)g_vb)[e2>>1] = pbf(c2+bv0, c3+bv1);
            } else {
                ((uint32_t*)g_ph)[e1>>1] = pbf(c0, c1);
                ((uint32_t*)g_ph)[e2>>1] = pbf(c2, c3);
            }
        }
}

// ---------------- kernel 3: sv = (q+pbv) . p^T, scattered to SHIFTED layout (bf16) ----------------
__global__ __launch_bounds__(256) void sv_mma() {
    __shared__ uint32_t Qs[128][36];
    __shared__ uint32_t Ps[128][36];

    const int n0 = blockIdx.x*128, m0 = blockIdx.y*128;
    const int bh = blockIdx.z;
    const int tid = threadIdx.x, lane = tid & 31, warp = tid >> 5;
    const int g = lane >> 2, tg = lane & 3;

    const uint32_t sQ = (uint32_t)__cvta_generic_to_shared(&Qs[0][0]);
    const uint32_t sP = (uint32_t)__cvta_generic_to_shared(&Ps[0][0]);
    #pragma unroll
    for (int i = 0; i < 4; i++) {
        const int c = tid + i*256;
        const int row = c >> 3, cw = (c & 7) * 4;
        cp16(sQ + (row*36 + cw)*4, g_qv + ((size_t)bh*TT + n0 + row)*DH + cw*2);
        cp16(sP + (row*36 + cw)*4, g_ph + ((size_t)bh*TT + m0 + row)*DH + cw*2);
    }
    cp_commit(); cp_wait<0>();
    __syncthreads();

    const int wr = (warp >> 1) * 32, wc = (warp & 1) * 64;
    float C[2][8][4] = {};
    #pragma unroll
    for (int ks = 0; ks < 4; ks++) {
        const int kw = ks * 8;
        uint32_t a0[4], a1[4];
        ldsmA(a0, &Qs[0][0], wr,      kw, 36, lane);
        ldsmA(a1, &Qs[0][0], wr + 16, kw, 36, lane);
        #pragma unroll
        for (int nb = 0; nb < 4; nb++) {
            uint32_t b[4];
            ldsmB(b, &Ps[0][0], wc + nb*16, kw, 36, lane);
            mma16(C[0][nb*2],   a0, b);
            mma16(C[0][nb*2+1], a0, b+2);
            mma16(C[1][nb*2],   a1, b);
            mma16(C[1][nb*2+1], a1, b+2);
        }
    }

    __nv_bfloat16* svb = g_sv + (size_t)bh * TT * MM;
    #pragma unroll
    for (int rs = 0; rs < 2; rs++)
        #pragma unroll
        for (int ns = 0; ns < 8; ns++) {
            const int rbase = n0 + wr + rs*16 + g;
            const int cbase = m0 + wc + ns*8 + tg*2;
            #pragma unroll
            for (int rr = 0; rr < 2; rr++) {
                const int r = rbase + rr*8;
                #pragma unroll
                for (int e = 0; e < 2; e++) {
                    const int cc = cbase + e;
                    const float val = C[rs][ns][rr*2+e];
                    int dr, dm;
                    if (cc >= MM-1-r) { dr = r;     dm = cc + r + 1 - MM; }
                    else              { dr = r - 1; dm = cc + r + 1; }
                    if (dr >= 0) svb[(size_t)dr * MM + dm] = __float2bfloat16(val);
                }
            }
        }
}

// ---------------- kernel 4: fused softmax + P.V ----------------
// P stays in registers: the S-tile fragment layout after QK^T IS the A-fragment
// layout for PV (a0: ns=2ks, a2: ns=2ks+1). No Ps smem, no P STS/LDSM.
// smem: Qs[128*36] Ks[2][64*36] Vs[2][64*36] = 55296 B
__global__ __launch_bounds__(256) void attn_mma() {
    extern __shared__ uint32_t dsm_at[];
    uint32_t* Qs = dsm_at;                       // [128][36] q+pbu
    uint32_t* Ks = Qs + 128*36;                  // [2][64][36] [m][k-pairs]
    uint32_t* Vs = Ks + 2*64*36;                 // [2][64][36] [m][c-pairs]

    const int n0 = blockIdx.x*128;
    const int bh = blockIdx.y;
    const int tid = threadIdx.x, lane = tid & 31, warp = tid >> 5;
    const int g = lane >> 2, tg = lane & 3;

    const uint32_t sQ = (uint32_t)__cvta_generic_to_shared(Qs);
    const uint32_t sK = (uint32_t)__cvta_generic_to_shared(Ks);
    const uint32_t sV = (uint32_t)__cvta_generic_to_shared(Vs);

    auto fillKV = [&](int st, int m0) {
        #pragma unroll
        for (int i = 0; i < 2; i++) {
            const int c = tid + i*256;
            const int row = c >> 3, cw = (c & 7) * 4;
            cp16(sK + ((st*64 + row)*36 + cw)*4,
                 g_kb + ((size_t)bh*TT + m0 + row)*DH + cw*2);
            cp16(sV + ((st*64 + row)*36 + cw)*4,
                 g_vb + ((size_t)bh*TT + m0 + row)*DH + cw*2);
        }
    };

    #pragma unroll
    for (int i = 0; i < 4; i++) {
        const int c = tid + i*256;
        const int row = c >> 3, cw = (c & 7) * 4;
        cp16(sQ + (row*36 + cw)*4, g_qu + ((size_t)bh*TT + n0 + row)*DH + cw*2);
    }
    cp_commit();
    fillKV(0, 0); cp_commit();

    cp_wait<1>();
    __syncthreads();
    uint32_t aq[4][4];
    #pragma unroll
    for (int ks = 0; ks < 4; ks++) ldsmA(aq[ks], Qs, warp*16, ks*8, 36, lane);

    float O[8][4] = {};
    float lst[2] = {0.f, 0.f};
    const __nv_bfloat16* svb = g_sv + (size_t)bh * TT * MM;
    const int rr1 = warp*16 + g;
    const int n1 = n0 + rr1, n2 = n1 + 8;

    for (int mt = 0; mt < MM/64; mt++) {
        const int m0 = mt * 64;
        if (mt < 15) { fillKV((mt+1)&1, m0 + 64); cp_commit(); cp_wait<1>(); }
        else cp_wait<0>();
        __syncthreads();
        const uint32_t* pK = Ks + (mt&1)*64*36;
        const uint32_t* pV = Vs + (mt&1)*64*36;

        // prefetch shifted pos-logit words (independent of K) to hide LDG latency
        uint32_t w1[8], w2[8];
        #pragma unroll
        for (int ns = 0; ns < 8; ns++) {
            const int mcb = m0 + ns*8 + tg*2;
            w1[ns] = ((const uint32_t*)svb)[((size_t)n1*MM + mcb) >> 1];
            w2[ns] = ((const uint32_t*)svb)[((size_t)n2*MM + mcb) >> 1];
        }

        // S = Qu . K^T
        float S[8][4] = {};
        #pragma unroll
        for (int ks = 0; ks < 4; ks++) {
            const int kw = ks * 8;
            #pragma unroll
            for (int nb = 0; nb < 4; nb++) {
                uint32_t b[4];
                ldsmB(b, pK, nb*16, kw, 36, lane);
                mma16(S[nb*2],   aq[ks], b);
                mma16(S[nb*2+1], aq[ks], b+2);
            }
        }

        // add shifted pos logits, zero pad slot, scale, exp, accumulate row sums
        float ps1 = 0.f, ps2 = 0.f;
        #pragma unroll
        for (int ns = 0; ns < 8; ns++) {
            const int mcb = m0 + ns*8 + tg*2;
            float s1x = __uint_as_float(w1[ns] << 16);
            float s1y = __uint_as_float(w1[ns] & 0xffff0000u);
            float s2x = __uint_as_float(w2[ns] << 16);
            float s2y = __uint_as_float(w2[ns] & 0xffff0000u);
            if (mcb   == n1+1) s1x = 0.f;
            if (mcb+1 == n1+1) s1y = 0.f;
            if (mcb   == n2+1) s2x = 0.f;
            if (mcb+1 == n2+1) s2y = 0.f;
            S[ns][0] = __expf((S[ns][0] + s1x) * 0.125f); ps1 += S[ns][0];
            S[ns][1] = __expf((S[ns][1] + s1y) * 0.125f); ps1 += S[ns][1];
            S[ns][2] = __expf((S[ns][2] + s2x) * 0.125f); ps2 += S[ns][2];
            S[ns][3] = __expf((S[ns][3] + s2y) * 0.125f); ps2 += S[ns][3];
        }
        ps1 += __shfl_xor_sync(0xffffffffu, ps1, 1);
        ps1 += __shfl_xor_sync(0xffffffffu, ps1, 2);
        ps2 += __shfl_xor_sync(0xffffffffu, ps2, 1);
        ps2 += __shfl_xor_sync(0xffffffffu, ps2, 2);
        lst[0] += ps1;
        lst[1] += ps2;

        // PV: P A-fragments built directly from S registers (no smem round trip)
        #pragma unroll
        for (int ks = 0; ks < 4; ks++) {
            uint32_t a[4];
            a[0] = pbf(S[2*ks][0],   S[2*ks][1]);
            a[1] = pbf(S[2*ks][2],   S[2*ks][3]);
            a[2] = pbf(S[2*ks+1][0], S[2*ks+1][1]);
            a[3] = pbf(S[2*ks+1][2], S[2*ks+1][3]);
            const int kw = ks * 8;
            #pragma unroll
            for (int nb = 0; nb < 4; nb++) {
                uint32_t b[4];
                ldsmBT(b, pV, nb*16, kw, 36, lane);
                mma16(O[nb*2],   a, b);
                mma16(O[nb*2+1], a, b+2);
            }
        }
        __syncthreads();
    }

    // epilogue -> g_ob [b][t][h][dh] bf16
    const int bb = bh >> 3, h = bh & 7;
    const float i1 = 1.f / lst[0], i2 = 1.f / lst[1];
    #pragma unroll
    for (int ns = 0; ns < 8; ns++) {
        const int col = ns*8 + tg*2;
        const size_t e1 = (((size_t)bb*TT + n1)*HH + h)*DH + col;
        const size_t e2 = (((size_t)bb*TT + n2)*HH + h)*DH + col;
        ((uint32_t*)g_ob)[e1>>1] = pbf(O[ns][0]*i1, O[ns][1]*i1);
        ((uint32_t*)g_ob)[e2>>1] = pbf(O[ns][2]*i2, O[ns][3]*i2);
    }
}

// ---------------- kernel 5: output projection + bias + residual ----------------
__global__ __launch_bounds__(256) void out_mma(const float* __restrict__ inputs,
                                               const float* __restrict__ projb,
                                               float* __restrict__ out) {
    __shared__ uint32_t As[2][128][20];
    __shared__ uint32_t Bs[2][128][20];
    const int bt0 = blockIdx.x*128, d0 = blockIdx.y*128;
    const int tid = threadIdx.x, lane = tid & 31, warp = tid >> 5;
    const int g = lane >> 2, tg = lane & 3;
    const int wr = (warp >> 1) * 32, wc = (warp & 1) * 64;

    const uint32_t sA = (uint32_t)__cvta_generic_to_shared(&As[0][0][0]);
    const uint32_t sB = (uint32_t)__cvta_generic_to_shared(&Bs[0][0][0]);

    auto fill = [&](int st, int k0) {
        #pragma unroll
        for (int i = 0; i < 2; i++) {
            const int c = tid + i*256;
            const int row = c >> 2, cw = (c & 3) * 4;
            cp16(sA + ((st*128 + row)*20 + cw)*4,
                 g_ob + (size_t)(bt0 + row)*DD + k0 + cw*2);
            cp16(sB + ((st*128 + row)*20 + cw)*4,
                 g_wo + (size_t)(d0 + row)*DD + k0 + cw*2);
        }
    };

    float C[2][8][4] = {};
    fill(0, 0); cp_commit();
    for (int kt = 0; kt < 16; kt++) {
        if (kt < 15) { fill((kt+1)&1, (kt+1)*32); cp_commit(); cp_wait<1>(); }
        else cp_wait<0>();
        __syncthreads();
        const uint32_t* pa = &As[kt&1][0][0];
        const uint32_t* pb = &Bs[kt&1][0][0];
        #pragma unroll
        for (int ks = 0; ks < 2; ks++) {
            const int kw = ks * 8;
            uint32_t a0[4], a1[4];
            ldsmA(a0, pa, wr,      kw, 20, lane);
            ldsmA(a1, pa, wr + 16, kw, 20, lane);
            #pragma unroll
            for (int nb = 0; nb < 4; nb++) {
                uint32_t bb[4];
                ldsmB(bb, pb, wc + nb*16, kw, 20, lane);
                mma16(C[0][nb*2],   a0, bb);
                mma16(C[0][nb*2+1], a0, bb+2);
                mma16(C[1][nb*2],   a1, bb);
                mma16(C[1][nb*2+1], a1, bb+2);
            }
        }
        __syncthreads();
    }

    #pragma unroll
    for (int rs = 0; rs < 2; rs++)
        #pragma unroll
        for (int ns = 0; ns < 8; ns++) {
            const int row = bt0 + wr + rs*16 + g;
            const int col = d0 + wc + ns*8 + tg*2;
            const float pb0 = projb[col], pb1 = projb[col+1];
            const float2 r1 = *(const float2*)&inputs[(size_t)row*DD + col];
            *(float2*)&out[(size_t)row*DD + col] =
                make_float2(C[rs][ns][0] + pb0 + r1.x, C[rs][ns][1] + pb1 + r1.y);
            const float2 r2 = *(const float2*)&inputs[(size_t)(row+8)*DD + col];
            *(float2*)&out[(size_t)(row+8)*DD + col] =
                make_float2(C[rs][ns][2] + pb0 + r2.x, C[rs][ns][3] + pb1 + r2.y);
        }
}

// ---------------- host ----------------
extern "C" void kernel_launch(void* const* d_in, const int* in_sizes, int n_in,
                              void* d_out, int out_size) {
    const float* inputs = (const float*)d_in[0];
    const float* pos    = (const float*)d_in[1];
    const float* gam    = (const float*)d_in[2];
    const float* bet    = (const float*)d_in[3];
    const float* w_q    = (const float*)d_in[4];
    const float* b_q    = (const float*)d_in[5];
    const float* w_k    = (const float*)d_in[6];
    const float* b_k    = (const float*)d_in[7];
    const float* w_v    = (const float*)d_in[8];
    const float* b_v    = (const float*)d_in[9];
    const float* w_p    = (const float*)d_in[10];
    const float* pbu    = (const float*)d_in[11];
    const float* pbv    = (const float*)d_in[12];
    const float* w_o    = (const float*)d_in[13];
    const float* b_o    = (const float*)d_in[14];
    float* out = (float*)d_out;

    const int attn_smem = (128*36 + 2*64*36 + 2*64*36) * 4;  // 55296
    cudaFuncSetAttribute(attn_mma, cudaFuncAttributeMaxDynamicSharedMemorySize, attn_smem);

    ln_kernel<<<BT, 256>>>(inputs, gam, bet);
    cvt_pos<<<BT*DD/512, 256>>>(pos);
    cvt_wt<<<dim3(DD/32, DH/32, 4*HH), dim3(32, 8)>>>(w_q, w_k, w_v, w_p);
    cvt_wo<<<dim3(DD/32, DD/32), dim3(32, 8)>>>(w_o);

    proj_all<<<dim3(BT/128, 16), 256>>>(b_q, b_k, b_v, pbu, pbv);

    sv_mma<<<dim3(TT/128, MM/128, BB*HH), 256>>>();

    attn_mma<<<dim3(TT/128, BB*HH), 256, attn_smem>>>();

    out_mma<<<dim3(BT/128, DD/128), 256>>>(inputs, b_o, out);
}

// round 16
// speedup vs baseline: 1.0088x; 1.0088x over previous
#include <cuda_runtime.h>
#include <cuda_bf16.h>
#include <stdint.h>
#include <math.h>

#define BB 8
#define TT 1024
#define DD 512
#define HH 8
#define DH 64
#define MM 1024
#define BT (BB*TT)

// ---------------- scratch (device globals; allocation-free) ----------------
__device__ __align__(16) __nv_bfloat16 g_xb[BT*DD];          // LN output bf16 [bt][d]
__device__ __align__(16) __nv_bfloat16 g_pb[BT*DD];          // pos bf16 [bt][d]
__device__ __align__(16) __nv_bfloat16 g_wt[4*HH*DH*DD];     // weights [m][h][n][k] bf16
__device__ __align__(16) __nv_bfloat16 g_wo[DD*DD];          // out-proj [d][k] bf16
__device__ __align__(16) __nv_bfloat16 g_qu[BB*HH*TT*DH];    // q + pbu  [bh][t][dh]
__device__ __align__(16) __nv_bfloat16 g_qv[BB*HH*TT*DH];    // q + pbv
__device__ __align__(16) __nv_bfloat16 g_kb[BB*HH*TT*DH];    // k
__device__ __align__(16) __nv_bfloat16 g_vb[BB*HH*TT*DH];    // v
__device__ __align__(16) __nv_bfloat16 g_ph[BB*HH*TT*DH];    // projected pos
__device__ __align__(16) __nv_bfloat16 g_ob[BT*DD];          // attn out [b][t][h][dh]
__device__ __align__(16) __nv_bfloat16 g_sv[(size_t)BB*HH*TT*MM];  // SHIFTED pos logits bf16

// ---------------- helpers ----------------
__device__ __forceinline__ uint32_t pbf(float lo, float hi) {
    uint32_t r;
    asm volatile("cvt.rn.bf16x2.f32 %0, %1, %2;" : "=r"(r) : "f"(hi), "f"(lo));
    return r;
}

__device__ __forceinline__ void mma16(float* d, const uint32_t* a, const uint32_t* b) {
    asm volatile(
        "mma.sync.aligned.m16n8k16.row.col.f32.bf16.bf16.f32 "
        "{%0,%1,%2,%3}, {%4,%5,%6,%7}, {%8,%9}, {%0,%1,%2,%3};\n"
        : "+f"(d[0]), "+f"(d[1]), "+f"(d[2]), "+f"(d[3])
        : "r"(a[0]), "r"(a[1]), "r"(a[2]), "r"(a[3]), "r"(b[0]), "r"(b[1]));
}

__device__ __forceinline__ void ldsm4(uint32_t* r, uint32_t addr) {
    asm volatile("ldmatrix.sync.aligned.m8n8.x4.shared.b16 {%0,%1,%2,%3}, [%4];"
                 : "=r"(r[0]), "=r"(r[1]), "=r"(r[2]), "=r"(r[3]) : "r"(addr));
}
__device__ __forceinline__ void ldsm4t(uint32_t* r, uint32_t addr) {
    asm volatile("ldmatrix.sync.aligned.m8n8.x4.trans.shared.b16 {%0,%1,%2,%3}, [%4];"
                 : "=r"(r[0]), "=r"(r[1]), "=r"(r[2]), "=r"(r[3]) : "r"(addr));
}

// A-fragment 16x16 bf16 from [row][k-pair] layout
__device__ __forceinline__ void ldsmA(uint32_t* a, const uint32_t* S, int rowbase,
                                      int kw, int ldw, int lane) {
    const int t = lane >> 3, rr = lane & 7;
    const uint32_t* p = S + (size_t)(rowbase + ((t & 1) << 3) + rr) * ldw + kw + ((t >> 1) << 2);
    ldsm4(a, (uint32_t)__cvta_generic_to_shared(p));
}
// B-fragments for two n-blocks from [n][k-pair] layout
__device__ __forceinline__ void ldsmB(uint32_t* b, const uint32_t* S, int nbase,
                                      int kw, int ldw, int lane) {
    const int t = lane >> 3, rr = lane & 7;
    const uint32_t* p = S + (size_t)(nbase + ((t >> 1) << 3) + rr) * ldw + kw + ((t & 1) << 2);
    ldsm4(b, (uint32_t)__cvta_generic_to_shared(p));
}
// B-fragments for two n-blocks from [k][n-pair] layout via ldmatrix.trans
__device__ __forceinline__ void ldsmBT(uint32_t* b, const uint32_t* S, int nbase,
                                       int kw, int ldw, int lane) {
    const int t = lane >> 3, rr = lane & 7;
    const uint32_t* p = S + (size_t)(kw*2 + ((t & 1) << 3) + rr) * ldw + (nbase >> 1) + ((t >> 1) << 2);
    ldsm4t(b, (uint32_t)__cvta_generic_to_shared(p));
}

__device__ __forceinline__ void cp16(uint32_t saddr, const void* gptr) {
    asm volatile("cp.async.cg.shared.global [%0], [%1], 16;" :: "r"(saddr), "l"(gptr));
}
__device__ __forceinline__ void cp_commit() { asm volatile("cp.async.commit_group;"); }
template<int N> __device__ __forceinline__ void cp_wait() {
    asm volatile("cp.async.wait_group %0;" :: "n"(N));
}

// ---------------- kernel 1: LayerNorm -> bf16 ----------------
__global__ void ln_kernel(const float* __restrict__ in,
                          const float* __restrict__ gamma,
                          const float* __restrict__ beta) {
    const int row = blockIdx.x;
    const int tid = threadIdx.x;
    const float2 v = ((const float2*)(in + (size_t)row * DD))[tid];
    __shared__ float red[8];

    float s = v.x + v.y;
    #pragma unroll
    for (int o = 16; o; o >>= 1) s += __shfl_xor_sync(0xffffffffu, s, o);
    if ((tid & 31) == 0) red[tid >> 5] = s;
    __syncthreads();
    float mean = 0.f;
    #pragma unroll
    for (int i = 0; i < 8; i++) mean += red[i];
    mean *= (1.0f / DD);
    __syncthreads();

    const float dx = v.x - mean, dy = v.y - mean;
    float sq = dx*dx + dy*dy;
    #pragma unroll
    for (int o = 16; o; o >>= 1) sq += __shfl_xor_sync(0xffffffffu, sq, o);
    if ((tid & 31) == 0) red[tid >> 5] = sq;
    __syncthreads();
    float var = 0.f;
    #pragma unroll
    for (int i = 0; i < 8; i++) var += red[i];
    var *= (1.0f / DD);

    const float inv = rsqrtf(var + 1e-3f);
    const int c0 = tid * 2;
    const float y0 = dx * inv * gamma[c0]   + beta[c0];
    const float y1 = dy * inv * gamma[c0+1] + beta[c0+1];
    ((uint32_t*)g_xb)[row * (DD/2) + tid] = pbf(y0, y1);
}

// ---------------- converters ----------------
__global__ void cvt_pos(const float* __restrict__ pos) {
    const int w = blockIdx.x * 256 + threadIdx.x;
    const float2 v = ((const float2*)pos)[w];
    ((uint32_t*)g_pb)[w] = pbf(v.x, v.y);
}

// weights [H][D][DH] -> g_wt [m][h][n][k]; 32x32 smem-tile transpose
__global__ void cvt_wt(const float* __restrict__ wq, const float* __restrict__ wk,
                       const float* __restrict__ wv, const float* __restrict__ wp) {
    __shared__ float tile[32][33];
    const int mh = blockIdx.z, m = mh >> 3, h = mh & 7;
    const int k0 = blockIdx.x * 32, n0 = blockIdx.y * 32;
    const float* W = (m == 0) ? wq : (m == 1) ? wk : (m == 2) ? wv : wp;
    const int tx = threadIdx.x, ty = threadIdx.y;   // 32 x 8
    #pragma unroll
    for (int i = 0; i < 4; i++) {
        const int k = k0 + ty + i*8;
        tile[ty + i*8][tx] = W[((size_t)h*DD + k)*DH + n0 + tx];
    }
    __syncthreads();
    #pragma unroll
    for (int i = 0; i < 4; i++) {
        const int n = n0 + ty + i*8;
        g_wt[((size_t)(mh*DH + n))*DD + k0 + tx] = __float2bfloat16(tile[tx][ty + i*8]);
    }
}

// proj_k [D][D] (k-major rows) -> g_wo [d][k]; 32x32 smem-tile transpose
__global__ void cvt_wo(const float* __restrict__ projk) {
    __shared__ float tile[32][33];
    const int k0 = blockIdx.x * 32, d0 = blockIdx.y * 32;
    const int tx = threadIdx.x, ty = threadIdx.y;
    #pragma unroll
    for (int i = 0; i < 4; i++) {
        const int k = k0 + ty + i*8;
        tile[ty + i*8][tx] = projk[(size_t)k*DD + d0 + tx];
    }
    __syncthreads();
    #pragma unroll
    for (int i = 0; i < 4; i++) {
        const int d = d0 + ty + i*8;
        g_wo[(size_t)d*DD + k0 + tx] = __float2bfloat16(tile[tx][ty + i*8]);
    }
}

// ---------------- kernel 2: merged projections (q,k,v,p) ----------------
__global__ __launch_bounds__(256) void proj_all(const float* __restrict__ b_q,
                                                const float* __restrict__ b_k,
                                                const float* __restrict__ b_v,
                                                const float* __restrict__ pbu,
                                                const float* __restrict__ pbv) {
    __shared__ uint32_t As[2][128][20];
    __shared__ uint32_t Bs[2][128][20];

    const int bt0 = blockIdx.x * 128;
    const int y = blockIdx.y, m = y >> 2, h0 = (y & 3) * 2;
    const __nv_bfloat16* Asrc = (m == 3) ? g_pb : g_xb;
    const int tid = threadIdx.x, lane = tid & 31, warp = tid >> 5;
    const int g = lane >> 2, tg = lane & 3;
    const int wr = (warp >> 1) * 32, wc = (warp & 1) * 64;

    const uint32_t sA = (uint32_t)__cvta_generic_to_shared(&As[0][0][0]);
    const uint32_t sB = (uint32_t)__cvta_generic_to_shared(&Bs[0][0][0]);

    auto fill = [&](int st, int k0) {
        #pragma unroll
        for (int i = 0; i < 2; i++) {
            const int c = tid + i*256;
            const int row = c >> 2, cw = (c & 3) * 4;
            cp16(sA + ((st*128 + row)*20 + cw)*4,
                 Asrc + (size_t)(bt0 + row)*DD + k0 + cw*2);
            const int h = h0 + (row >> 6), n = row & 63;
            cp16(sB + ((st*128 + row)*20 + cw)*4,
                 g_wt + ((size_t)((m*HH + h)*DH + n))*DD + k0 + cw*2);
        }
    };

    float C[2][8][4] = {};
    fill(0, 0); cp_commit();
    for (int kt = 0; kt < 16; kt++) {
        if (kt < 15) { fill((kt+1)&1, (kt+1)*32); cp_commit(); cp_wait<1>(); }
        else cp_wait<0>();
        __syncthreads();
        const uint32_t* pa = &As[kt&1][0][0];
        const uint32_t* pb = &Bs[kt&1][0][0];
        #pragma unroll
        for (int ks = 0; ks < 2; ks++) {
            const int kw = ks * 8;
            uint32_t a0[4], a1[4];
            ldsmA(a0, pa, wr,      kw, 20, lane);
            ldsmA(a1, pa, wr + 16, kw, 20, lane);
            #pragma unroll
            for (int nb = 0; nb < 4; nb++) {
                uint32_t bb[4];
                ldsmB(bb, pb, wc + nb*16, kw, 20, lane);
                mma16(C[0][nb*2],   a0, bb);
                mma16(C[0][nb*2+1], a0, bb+2);
                mma16(C[1][nb*2],   a1, bb);
                mma16(C[1][nb*2+1], a1, bb+2);
            }
        }
        __syncthreads();
    }

    const int b = bt0 >> 10, t0l = bt0 & (TT-1);
    #pragma unroll
    for (int rs = 0; rs < 2; rs++)
        #pragma unroll
        for (int ns = 0; ns < 8; ns++) {
            const int r = wr + rs*16 + g;
            const int col = wc + ns*8 + tg*2;
            const int h = h0 + (col >> 6), dh = col & 63;
            const int t1 = t0l + r, t2 = t1 + 8;
            const size_t e1 = (((size_t)b*HH + h)*TT + t1)*DH + dh;
            const size_t e2 = (((size_t)b*HH + h)*TT + t2)*DH + dh;
            const float c0 = C[rs][ns][0], c1 = C[rs][ns][1];
            const float c2 = C[rs][ns][2], c3 = C[rs][ns][3];
            if (m == 0) {
                const float bq0 = b_q[h*DH+dh], bq1 = b_q[h*DH+dh+1];
                const float u0 = pbu[h*DH+dh], u1 = pbu[h*DH+dh+1];
                const float v0 = pbv[h*DH+dh], v1 = pbv[h*DH+dh+1];
                ((uint32_t*)g_qu)[e1>>1] = pbf(c0+bq0+u0, c1+bq1+u1);
                ((uint32_t*)g_qu)[e2>>1] = pbf(c2+bq0+u0, c3+bq1+u1);
                ((uint32_t*)g_qv)[e1>>1] = pbf(c0+bq0+v0, c1+bq1+v1);
                ((uint32_t*)g_qv)[e2>>1] = pbf(c2+bq0+v0, c3+bq1+v1);
            } else if (m == 1) {
                const float bk0 = b_k[h*DH+dh], bk1 = b_k[h*DH+dh+1];
                ((uint32_t*)g_kb)[e1>>1] = pbf(c0+bk0, c1+bk1);
                ((uint32_t*)g_kb)[e2>>1] = pbf(c2+bk0, c3+bk1);
            } else if (m == 2) {
                const float bv0 = b_v[h*DH+dh], bv1 = b_v[h*DH+dh+1];
                ((uint32_t*)g_vb)[e1>>1] = pbf(c0+bv0, c1+bv1);
                ((uint32_t*)g_vb)[e2>>1] = pbf(c2+bv0, c3+bv1);
            } else {
                ((uint32_t*)g_ph)[e1>>1] = pbf(c0, c1);
                ((uint32_t*)g_ph)[e2>>1] = pbf(c2, c3);
            }
        }
}

// ---------------- kernel 3: sv = (q+pbv) . p^T, scattered to SHIFTED layout (bf16) ----------------
__global__ __launch_bounds__(256) void sv_mma() {
    __shared__ uint32_t Qs[128][36];
    __shared__ uint32_t Ps[128][36];

    const int n0 = blockIdx.x*128, m0 = blockIdx.y*128;
    const int bh = blockIdx.z;
    const int tid = threadIdx.x, lane = tid & 31, warp = tid >> 5;
    const int g = lane >> 2, tg = lane & 3;

    const uint32_t sQ = (uint32_t)__cvta_generic_to_shared(&Qs[0][0]);
    const uint32_t sP = (uint32_t)__cvta_generic_to_shared(&Ps[0][0]);
    #pragma unroll
    for (int i = 0; i < 4; i++) {
        const int c = tid + i*256;
        const int row = c >> 3, cw = (c & 7) * 4;
        cp16(sQ + (row*36 + cw)*4, g_qv + ((size_t)bh*TT + n0 + row)*DH + cw*2);
        cp16(sP + (row*36 + cw)*4, g_ph + ((size_t)bh*TT + m0 + row)*DH + cw*2);
    }
    cp_commit(); cp_wait<0>();
    __syncthreads();

    const int wr = (warp >> 1) * 32, wc = (warp & 1) * 64;
    float C[2][8][4] = {};
    #pragma unroll
    for (int ks = 0; ks < 4; ks++) {
        const int kw = ks * 8;
        uint32_t a0[4], a1[4];
        ldsmA(a0, &Qs[0][0], wr,      kw, 36, lane);
        ldsmA(a1, &Qs[0][0], wr + 16, kw, 36, lane);
        #pragma unroll
        for (int nb = 0; nb < 4; nb++) {
            uint32_t b[4];
            ldsmB(b, &Ps[0][0], wc + nb*16, kw, 36, lane);
            mma16(C[0][nb*2],   a0, b);
            mma16(C[0][nb*2+1], a0, b+2);
            mma16(C[1][nb*2],   a1, b);
            mma16(C[1][nb*2+1], a1, b+2);
        }
    }

    __nv_bfloat16* svb = g_sv + (size_t)bh * TT * MM;
    #pragma unroll
    for (int rs = 0; rs < 2; rs++)
        #pragma unroll
        for (int ns = 0; ns < 8; ns++) {
            const int rbase = n0 + wr + rs*16 + g;
            const int cbase = m0 + wc + ns*8 + tg*2;
            #pragma unroll
            for (int rr = 0; rr < 2; rr++) {
                const int r = rbase + rr*8;
                #pragma unroll
                for (int e = 0; e < 2; e++) {
                    const int cc = cbase + e;
                    const float val = C[rs][ns][rr*2+e];
                    int dr, dm;
                    if (cc >= MM-1-r) { dr = r;     dm = cc + r + 1 - MM; }
                    else              { dr = r - 1; dm = cc + r + 1; }
                    if (dr >= 0) svb[(size_t)dr * MM + dm] = __float2bfloat16(val);
                }
            }
        }
}

// ---------------- kernel 4: fused softmax + P.V ----------------
// P stays in registers (S-fragments ARE the PV A-fragments). 3-stage KV cp.async
// ring: fill of tile mt+2 reuses buffer of tile mt-1, which the single top-of-
// iteration barrier already ordered -> ONE __syncthreads per m-tile.
// Softmax: exp((s+sv)/8) == exp2((s+sv)*0.125*log2e) -- constant folded.
// smem: Qs[128*36] Ks[3][64*36] Vs[3][64*36] = 73728 B
__global__ __launch_bounds__(256) void attn_mma() {
    extern __shared__ uint32_t dsm_at[];
    uint32_t* Qs = dsm_at;                       // [128][36] q+pbu
    uint32_t* Ks = Qs + 128*36;                  // [3][64][36] [m][k-pairs]
    uint32_t* Vs = Ks + 3*64*36;                 // [3][64][36] [m][c-pairs]

    const int n0 = blockIdx.x*128;
    const int bh = blockIdx.y;
    const int tid = threadIdx.x, lane = tid & 31, warp = tid >> 5;
    const int g = lane >> 2, tg = lane & 3;

    const uint32_t sQ = (uint32_t)__cvta_generic_to_shared(Qs);
    const uint32_t sK = (uint32_t)__cvta_generic_to_shared(Ks);
    const uint32_t sV = (uint32_t)__cvta_generic_to_shared(Vs);

    auto fillKV = [&](int st, int m0) {
        #pragma unroll
        for (int i = 0; i < 2; i++) {
            const int c = tid + i*256;
            const int row = c >> 3, cw = (c & 7) * 4;
            cp16(sK + ((st*64 + row)*36 + cw)*4,
                 g_kb + ((size_t)bh*TT + m0 + row)*DH + cw*2);
            cp16(sV + ((st*64 + row)*36 + cw)*4,
                 g_vb + ((size_t)bh*TT + m0 + row)*DH + cw*2);
        }
    };

    // prologue: Q group, then KV stages 0 and 1 (3 commit groups total)
    #pragma unroll
    for (int i = 0; i < 4; i++) {
        const int c = tid + i*256;
        const int row = c >> 3, cw = (c & 7) * 4;
        cp16(sQ + (row*36 + cw)*4, g_qu + ((size_t)bh*TT + n0 + row)*DH + cw*2);
    }
    cp_commit();
    fillKV(0, 0);  cp_commit();
    fillKV(1, 64); cp_commit();

    cp_wait<2>();            // Q ready (KV0, KV1 may still be in flight)
    __syncthreads();
    uint32_t aq[4][4];
    #pragma unroll
    for (int ks = 0; ks < 4; ks++) ldsmA(aq[ks], Qs, warp*16, ks*8, 36, lane);

    float O[8][4] = {};
    float lst[2] = {0.f, 0.f};
    const __nv_bfloat16* svb = g_sv + (size_t)bh * TT * MM;
    const int rr1 = warp*16 + g;
    const int n1 = n0 + rr1, n2 = n1 + 8;
    const float C2 = 0.125f * 1.44269504f;   // 1/8 * log2(e)

    for (int mt = 0; mt < MM/64; mt++) {
        const int m0 = mt * 64;
        if (mt < 15) cp_wait<1>(); else cp_wait<0>();   // KV(mt) ready
        __syncthreads();                                 // all warps done with tile mt-1
        if (mt + 2 <= 15) { fillKV((mt+2)%3, (mt+2)*64); cp_commit(); }
        const uint32_t* pK = Ks + (mt%3)*64*36;
        const uint32_t* pV = Vs + (mt%3)*64*36;

        // prefetch shifted pos-logit words (independent of K) to hide LDG latency
        uint32_t w1[8], w2[8];
        #pragma unroll
        for (int ns = 0; ns < 8; ns++) {
            const int mcb = m0 + ns*8 + tg*2;
            w1[ns] = ((const uint32_t*)svb)[((size_t)n1*MM + mcb) >> 1];
            w2[ns] = ((const uint32_t*)svb)[((size_t)n2*MM + mcb) >> 1];
        }

        // S = Qu . K^T
        float S[8][4] = {};
        #pragma unroll
        for (int ks = 0; ks < 4; ks++) {
            const int kw = ks * 8;
            #pragma unroll
            for (int nb = 0; nb < 4; nb++) {
                uint32_t b[4];
                ldsmB(b, pK, nb*16, kw, 36, lane);
                mma16(S[nb*2],   aq[ks], b);
                mma16(S[nb*2+1], aq[ks], b+2);
            }
        }

        // add shifted pos logits, zero pad slot, exp2 with folded scale, row sums
        float ps1 = 0.f, ps2 = 0.f;
        #pragma unroll
        for (int ns = 0; ns < 8; ns++) {
            const int mcb = m0 + ns*8 + tg*2;
            float s1x = __uint_as_float(w1[ns] << 16);
            float s1y = __uint_as_float(w1[ns] & 0xffff0000u);
            float s2x = __uint_as_float(w2[ns] << 16);
            float s2y = __uint_as_float(w2[ns] & 0xffff0000u);
            if (mcb   == n1+1) s1x = 0.f;
            if (mcb+1 == n1+1) s1y = 0.f;
            if (mcb   == n2+1) s2x = 0.f;
            if (mcb+1 == n2+1) s2y = 0.f;
            S[ns][0] = exp2f((S[ns][0] + s1x) * C2); ps1 += S[ns][0];
            S[ns][1] = exp2f((S[ns][1] + s1y) * C2); ps1 += S[ns][1];
            S[ns][2] = exp2f((S[ns][2] + s2x) * C2); ps2 += S[ns][2];
            S[ns][3] = exp2f((S[ns][3] + s2y) * C2); ps2 += S[ns][3];
        }
        ps1 += __shfl_xor_sync(0xffffffffu, ps1, 1);
        ps1 += __shfl_xor_sync(0xffffffffu, ps1, 2);
        ps2 += __shfl_xor_sync(0xffffffffu, ps2, 1);
        ps2 += __shfl_xor_sync(0xffffffffu, ps2, 2);
        lst[0] += ps1;
        lst[1] += ps2;

        // PV: P A-fragments built directly from S registers
        #pragma unroll
        for (int ks = 0; ks < 4; ks++) {
            uint32_t a[4];
            a[0] = pbf(S[2*ks][0],   S[2*ks][1]);
            a[1] = pbf(S[2*ks][2],   S[2*ks][3]);
            a[2] = pbf(S[2*ks+1][0], S[2*ks+1][1]);
            a[3] = pbf(S[2*ks+1][2], S[2*ks+1][3]);
            const int kw = ks * 8;
            #pragma unroll
            for (int nb = 0; nb < 4; nb++) {
                uint32_t b[4];
                ldsmBT(b, pV, nb*16, kw, 36, lane);
                mma16(O[nb*2],   a, b);
                mma16(O[nb*2+1], a, b+2);
            }
        }
    }

    // epilogue -> g_ob [b][t][h][dh] bf16
    const int bb = bh >> 3, h = bh & 7;
    const float i1 = 1.f / lst[0], i2 = 1.f / lst[1];
    #pragma unroll
    for (int ns = 0; ns < 8; ns++) {
        const int col = ns*8 + tg*2;
        const size_t e1 = (((size_t)bb*TT + n1)*HH + h)*DH + col;
        const size_t e2 = (((size_t)bb*TT + n2)*HH + h)*DH + col;
        ((uint32_t*)g_ob)[e1>>1] = pbf(O[ns][0]*i1, O[ns][1]*i1);
        ((uint32_t*)g_ob)[e2>>1] = pbf(O[ns][2]*i2, O[ns][3]*i2);
    }
}

// ---------------- kernel 5: output projection + bias + residual ----------------
__global__ __launch_bounds__(256) void out_mma(const float* __restrict__ inputs,
                                               const float* __restrict__ projb,
                                               float* __restrict__ out) {
    __shared__ uint32_t As[2][128][20];
    __shared__ uint32_t Bs[2][128][20];
    const int bt0 = blockIdx.x*128, d0 = blockIdx.y*128;
    const int tid = threadIdx.x, lane = tid & 31, warp = tid >> 5;
    const int g = lane >> 2, tg = lane & 3;
    const int wr = (warp >> 1) * 32, wc = (warp & 1) * 64;

    const uint32_t sA = (uint32_t)__cvta_generic_to_shared(&As[0][0][0]);
    const uint32_t sB = (uint32_t)__cvta_generic_to_shared(&Bs[0][0][0]);

    auto fill = [&](int st, int k0) {
        #pragma unroll
        for (int i = 0; i < 2; i++) {
            const int c = tid + i*256;
            const int row = c >> 2, cw = (c & 3) * 4;
            cp16(sA + ((st*128 + row)*20 + cw)*4,
                 g_ob + (size_t)(bt0 + row)*DD + k0 + cw*2);
            cp16(sB + ((st*128 + row)*20 + cw)*4,
                 g_wo + (size_t)(d0 + row)*DD + k0 + cw*2);
        }
    };

    float C[2][8][4] = {};
    fill(0, 0); cp_commit();
    for (int kt = 0; kt < 16; kt++) {
        if (kt < 15) { fill((kt+1)&1, (kt+1)*32); cp_commit(); cp_wait<1>(); }
        else cp_wait<0>();
        __syncthreads();
        const uint32_t* pa = &As[kt&1][0][0];
        const uint32_t* pb = &Bs[kt&1][0][0];
        #pragma unroll
        for (int ks = 0; ks < 2; ks++) {
            const int kw = ks * 8;
            uint32_t a0[4], a1[4];
            ldsmA(a0, pa, wr,      kw, 20, lane);
            ldsmA(a1, pa, wr + 16, kw, 20, lane);
            #pragma unroll
            for (int nb = 0; nb < 4; nb++) {
                uint32_t bb[4];
                ldsmB(bb, pb, wc + nb*16, kw, 20, lane);
                mma16(C[0][nb*2],   a0, bb);
                mma16(C[0][nb*2+1], a0, bb+2);
                mma16(C[1][nb*2],   a1, bb);
                mma16(C[1][nb*2+1], a1, bb+2);
            }
        }
        __syncthreads();
    }

    #pragma unroll
    for (int rs = 0; rs < 2; rs++)
        #pragma unroll
        for (int ns = 0; ns < 8; ns++) {
            const int row = bt0 + wr + rs*16 + g;
            const int col = d0 + wc + ns*8 + tg*2;
            const float pb0 = projb[col], pb1 = projb[col+1];
            const float2 r1 = *(const float2*)&inputs[(size_t)row*DD + col];
            *(float2*)&out[(size_t)row*DD + col] =
                make_float2(C[rs][ns][0] + pb0 + r1.x, C[rs][ns][1] + pb1 + r1.y);
            const float2 r2 = *(const float2*)&inputs[(size_t)(row+8)*DD + col];
            *(float2*)&out[(size_t)(row+8)*DD + col] =
                make_float2(C[rs][ns][2] + pb0 + r2.x, C[rs][ns][3] + pb1 + r2.y);
        }
}

// ---------------- host ----------------
extern "C" void kernel_launch(void* const* d_in, const int* in_sizes, int n_in,
                              void* d_out, int out_size) {
    const float* inputs = (const float*)d_in[0];
    const float* pos    = (const float*)d_in[1];
    const float* gam    = (const float*)d_in[2];
    const float* bet    = (const float*)d_in[3];
    const float* w_q    = (const float*)d_in[4];
    const float* b_q    = (const float*)d_in[5];
    const float* w_k    = (const float*)d_in[6];
    const float* b_k    = (const float*)d_in[7];
    const float* w_v    = (const float*)d_in[8];
    const float* b_v    = (const float*)d_in[9];
    const float* w_p    = (const float*)d_in[10];
    const float* pbu    = (const float*)d_in[11];
    const float* pbv    = (const float*)d_in[12];
    const float* w_o    = (const float*)d_in[13];
    const float* b_o    = (const float*)d_in[14];
    float* out = (float*)d_out;

    const int attn_smem = (128*36 + 3*64*36 + 3*64*36) * 4;  // 73728
    cudaFuncSetAttribute(attn_mma, cudaFuncAttributeMaxDynamicSharedMemorySize, attn_smem);

    ln_kernel<<<BT, 256>>>(inputs, gam, bet);
    cvt_pos<<<BT*DD/512, 256>>>(pos);
    cvt_wt<<<dim3(DD/32, DH/32, 4*HH), dim3(32, 8)>>>(w_q, w_k, w_v, w_p);
    cvt_wo<<<dim3(DD/32, DD/32), dim3(32, 8)>>>(w_o);

    proj_all<<<dim3(BT/128, 16), 256>>>(b_q, b_k, b_v, pbu, pbv);

    sv_mma<<<dim3(TT/128, MM/128, BB*HH), 256>>>();

    attn_mma<<<dim3(TT/128, BB*HH), 256, attn_smem>>>();

    out_mma<<<dim3(BT/128, DD/128), 256>>>(inputs, b_o, out);
}